// round 6
// baseline (speedup 1.0000x reference)
#include <cuda_runtime.h>
#include <math.h>

#define BSZ 4
#define CC  4
#define NN  2048
#define DD  16
#define KK  32
#define MM  64
#define FULLM 0xffffffffu
typedef unsigned long long ull;
#define INF32 0xffffffffu
#define INF64 0xFFFFFFFFFFFFFFFFull

// scratch (allocation-free rule: device globals)
__device__ int   g_nbr  [BSZ*CC*NN*KK];
__device__ float g_theta[BSZ*CC*NN*KK];
__device__ float g_gate [BSZ*CC*NN*KK];
__device__ float g_gsum [BSZ*CC*NN];

__device__ __forceinline__ ull warpmin64(ull p) {
    #pragma unroll
    for (int o = 16; o; o >>= 1) {
        ull q = __shfl_xor_sync(FULLM, p, o);
        if (q < p) p = q;
    }
    return p;
}

// sorted top-2 insert on u32 (d, j); strict < keeps earlier j on ties
#define INS2(dv, jv, h0d, h0j, h1d, h1j) do {                              \
    bool c1 = (dv) < (h1d); bool c0 = (dv) < (h0d);                        \
    (h1d) = c0 ? (h0d) : (c1 ? (dv) : (h1d));                              \
    (h1j) = c0 ? (h0j) : (c1 ? (jv) : (h1j));                              \
    (h0d) = c0 ? (dv) : (h0d);                                             \
    (h0j) = c0 ? (jv) : (h0j);                                             \
} while (0)

// ---------------------------------------------------------------------------
// Kernel 1 v6: 2 rows/warp, u32 keys, per-lane top-2 heads, REDUX extraction,
// rare exact refill. 32KB smem, occupancy 2 (64 regs -> no spills).
// ---------------------------------------------------------------------------
__device__ __forceinline__ void refill2(
    int w, unsigned dL, unsigned jL, float4 pi, int lane,
    unsigned& h0d, unsigned& h0j, unsigned& h1d, unsigned& h1j,
    const float4* spos)
{
    const ull L = ((ull)dL << 32) | jL;           // largest extracted so far
    const int j1 = lane*32 + w, j2 = j1 + 1024;
    float4 a  = spos[j1];
    float4 bb = spos[j2];
    float dota = fmaf(pi.z, a.z,  fmaf(pi.y, a.y,  pi.x * a.x));
    float dotb = fmaf(pi.z, bb.z, fmaf(pi.y, bb.y, pi.x * bb.x));
    float da = fmaxf(fmaf(-2.f, dota, a.w)  + pi.w, 0.f);
    float db = fmaxf(fmaf(-2.f, dotb, bb.w) + pi.w, 0.f);
    ull k1 = ((ull)__float_as_uint(da) << 32) | (unsigned)j1;
    ull k2 = ((ull)__float_as_uint(db) << 32) | (unsigned)j2;
    if (k1 <= L) k1 = INF64;                      // all remaining keys > L
    if (k2 <= L) k2 = INF64;
    #pragma unroll
    for (int r = 0; r < 2; r++) {
        ull m  = (k1 < k2) ? k1 : k2;
        ull wm = warpmin64(m);
        if (lane == w) {
            unsigned wd = (unsigned)(wm >> 32), wj = (unsigned)wm;
            if (r == 0) { h0d = wd; h0j = wj; }
            else        { h1d = wd; h1j = wj; }
        }
        if (k1 == wm) k1 = INF64; else if (k2 == wm) k2 = INF64;
    }
}

__device__ __forceinline__ void emit_row(
    int slice, int b, int i, float4 pi, unsigned nbd, int nbj,
    float Spos, const float* node_mask, const float4* spos, int lane)
{
    const float mk   = node_mask[b*NN + i];
    const float dist = __uint_as_float(nbd);
    const int   nb   = nbj;

    const int nb0 = __shfl_sync(FULLM, nbj, 0);
    float4 pn0 = spos[nb0];
    float d0x = pn0.x - pi.x, d0y = pn0.y - pi.y, d0z = pn0.z - pi.z;
    float n0  = sqrtf(d0x*d0x + d0y*d0y + d0z*d0z);
    float inv0 = 1.f / fmaxf(n0, 1e-12f);
    d0x *= inv0; d0y *= inv0; d0z *= inv0;

    float cosv = 1.f;
    if (lane > 0) {
        float4 pn = spos[nb];
        float dx = pn.x - pi.x, dy = pn.y - pi.y, dz = pn.z - pi.z;
        float nrm = sqrtf(dx*dx + dy*dy + dz*dz);
        float inv = 1.f / fmaxf(nrm, 1e-12f);
        cosv = (dx*d0x + dy*d0y + dz*d0z) * inv;
    }
    const float gb   = fmaxf(dist * Spos, 0.f) * mk;
    const float gate = 1.f / (1.f + __expf(-gb));

    float G = gate;
    #pragma unroll
    for (int o = 16; o; o >>= 1) G += __shfl_xor_sync(FULLM, G, o);

    const size_t base = ((size_t)slice * NN + i) * KK;
    g_nbr  [base + lane] = nb;
    g_theta[base + lane] = cosv * mk;
    g_gate [base + lane] = gate;
    if (lane == 0) g_gsum[(size_t)slice*NN + i] = G;
}

__global__ __launch_bounds__(512, 2) void knn_kernel(
    const float* __restrict__ pos, const float* __restrict__ node_mask,
    const float* __restrict__ rw1, const float* __restrict__ rw2)
{
    __shared__ float4 spos[NN];            // 32KB
    __shared__ float sSpos;

    const int tid  = threadIdx.x;
    const int warp = tid >> 5;
    const int lane = tid & 31;
    const int slice = blockIdx.y;          // b*C + c
    const int b     = slice >> 2;
    const float* p  = pos + (size_t)slice * NN * 3;

    for (int j = tid; j < NN; j += 512) {
        float x = p[3*j], y = p[3*j+1], z = p[3*j+2];
        float q = fmaf(z, z, fmaf(y, y, x*x));
        spos[j] = make_float4(x, y, z, q);
    }

    // gate MLP collapses: relu(sum_m relu(d*w1)*w2) = relu(d*Spos) for d>=0
    if (tid < 32) {
        float a1 = rw1[tid],    w1v = rw2[tid];
        float a2 = rw1[tid+32], w2v = rw2[tid+32];
        float sp = fmaf(fmaxf(a1, 0.f), w1v, fmaxf(a2, 0.f) * w2v);
        #pragma unroll
        for (int o = 16; o; o >>= 1) sp += __shfl_xor_sync(FULLM, sp, o);
        if (tid == 0) sSpos = sp;
    }
    __syncthreads();

    const int iA = blockIdx.x * 32 + warp * 2;
    const int iB = iA + 1;
    const float4 piA = spos[iA];
    const float4 piB = spos[iB];

    // distance pass: lane owns segment {j : j%32 == lane}; sorted top-2/row
    unsigned a0d = INF32, a1d = INF32, a0j = 0, a1j = 0;
    unsigned b0d = INF32, b1d = INF32, b0j = 0, b1j = 0;
    #pragma unroll 4
    for (int t = 0; t < 64; t++) {
        const unsigned j = (unsigned)(t*32 + lane);
        float4 pj = spos[j];
        float dotA = fmaf(piA.z, pj.z, fmaf(piA.y, pj.y, piA.x * pj.x));
        float dA   = fmaxf(fmaf(-2.f, dotA, pj.w) + piA.w, 0.f);
        unsigned uA = __float_as_uint(dA);
        INS2(uA, j, a0d, a0j, a1d, a1j);
        float dotB = fmaf(piB.z, pj.z, fmaf(piB.y, pj.y, piB.x * pj.x));
        float dB   = fmaxf(fmaf(-2.f, dotB, pj.w) + piB.w, 0.f);
        unsigned uB = __float_as_uint(dB);
        INS2(uB, j, b0d, b0j, b1d, b1j);
    }

    // extract 33 smallest ascending (d, j) for both rows; lane e-1 keeps e-th
    unsigned nbdA = 0, nbdB = 0; int nbjA = 0, nbjB = 0;
    #pragma unroll 1
    for (int e = 0; e <= 32; e++) {
        unsigned dminA = __reduce_min_sync(FULLM, a0d);
        unsigned cjA   = (a0d == dminA) ? a0j : INF32;
        unsigned jminA = __reduce_min_sync(FULLM, cjA);
        unsigned dminB = __reduce_min_sync(FULLM, b0d);
        unsigned cjB   = (b0d == dminB) ? b0j : INF32;
        unsigned jminB = __reduce_min_sync(FULLM, cjB);
        if (lane == e - 1) {
            nbdA = dminA; nbjA = (int)jminA;
            nbdB = dminB; nbjB = (int)jminB;
        }
        if (e == 32) break;
        const int wA = (int)(jminA & 31u);
        const int wB = (int)(jminB & 31u);
        if (lane == wA) { a0d = a1d; a0j = a1j; a1d = INF32; }
        if (lane == wB) { b0d = b1d; b0j = b1j; b1d = INF32; }
        unsigned hwA = __shfl_sync(FULLM, a0d, wA);
        unsigned hwB = __shfl_sync(FULLM, b0d, wB);
        if (hwA == INF32)
            refill2(wA, dminA, jminA, piA, lane, a0d, a0j, a1d, a1j, spos);
        if (hwB == INF32)
            refill2(wB, dminB, jminB, piB, lane, b0d, b0j, b1d, b1j, spos);
    }

    const float Spos = sSpos;
    emit_row(slice, b, iA, piA, nbdA, nbjA, Spos, node_mask, spos, lane);
    emit_row(slice, b, iB, piB, nbdB, nbjB, Spos, node_mask, spos, lane);
}

// ---------------------------------------------------------------------------
// Kernel 2 v6: 64 nodes/block (grid 128, one wave), in-block aw transpose,
// gather + dual GEMV with 4m x 4n tile. 100KB dynamic smem.
// ---------------------------------------------------------------------------
#define O2_SAWT 0          // [f][64]         8192 floats
#define O2_SU   8192       // [f][n pitch68]  8704
#define O2_STH  16896      // [f][n pitch68]  8704
#define O2_ARAW 8192       // overlay [64][129] = 8256 (dead before su/sth)
#define SM2F    25600      // floats -> 102400 bytes

__global__ __launch_bounds__(256) void fuse_kernel(
    const float* __restrict__ node_fea, const float* __restrict__ node_mask,
    const float* __restrict__ aw, const float* __restrict__ sw,
    float* __restrict__ out)
{
    extern __shared__ float sm2[];
    float* sawT = sm2 + O2_SAWT;
    float* su   = sm2 + O2_SU;
    float* sth  = sm2 + O2_STH;
    float* araw = sm2 + O2_ARAW;

    const int tid = threadIdx.x;
    const int b   = blockIdx.x >> 5;       // 32 blocks per batch
    const int n0  = (blockIdx.x & 31) * 64;

    // transpose aw [64 m][128 f] -> sawT [f][64 m] via padded staging
    for (int idx = tid; idx < MM*128; idx += 256) {
        int m = idx >> 7, f = idx & 127;
        araw[m*129 + f] = aw[idx];
    }
    __syncthreads();
    for (int idx = tid; idx < MM*128; idx += 256) {
        int f = idx >> 6, m = idx & 63;
        sawT[idx] = araw[m*129 + f];
    }
    __syncthreads();                       // araw dead; su/sth safe now

    // stage theta -> [f = k*4+c][n]
    for (int idx = tid; idx < 8192; idx += 256) {
        int c = idx >> 11, r = idx & 2047, n = r >> 5, k = r & 31;
        sth[(k*4 + c)*68 + n] =
            g_theta[(((size_t)(b*CC + c))*NN + n0 + n)*KK + k];
    }

    // phase A: thread = (c, nn) builds all 32 f-rows of su for its (c, node)
    {
        const int c = tid >> 6, nn = tid & 63;
        const float* nf = node_fea + (size_t)(b*CC + c) * NN * DD;
        const float mk = node_mask[b*NN + n0 + nn];
        const float G  = g_gsum[(size_t)(b*CC + c)*NN + n0 + nn];
        const size_t eb = ((size_t)(b*CC + c)*NN + n0 + nn) * KK;

        float4 a0 = {0,0,0,0}, a1 = {0,0,0,0}, a2 = {0,0,0,0}, a3 = {0,0,0,0};
        #pragma unroll 2
        for (int k4 = 0; k4 < 8; k4++) {
            float4 g4 = __ldg((const float4*)(g_gate + eb) + k4);
            int4   n4 = __ldg((const int4*)  (g_nbr  + eb) + k4);
            const float gs[4] = {g4.x, g4.y, g4.z, g4.w};
            const int   ns[4] = {n4.x, n4.y, n4.z, n4.w};
            #pragma unroll
            for (int e = 0; e < 4; e++) {
                const float4* vp = (const float4*)(nf + (size_t)ns[e]*DD);
                float4 v0 = __ldg(vp),     v1 = __ldg(vp + 1);
                float4 v2 = __ldg(vp + 2), v3 = __ldg(vp + 3);
                float g = gs[e];
                a0.x = fmaf(g, v0.x, a0.x); a0.y = fmaf(g, v0.y, a0.y);
                a0.z = fmaf(g, v0.z, a0.z); a0.w = fmaf(g, v0.w, a0.w);
                a1.x = fmaf(g, v1.x, a1.x); a1.y = fmaf(g, v1.y, a1.y);
                a1.z = fmaf(g, v1.z, a1.z); a1.w = fmaf(g, v1.w, a1.w);
                a2.x = fmaf(g, v2.x, a2.x); a2.y = fmaf(g, v2.y, a2.y);
                a2.z = fmaf(g, v2.z, a2.z); a2.w = fmaf(g, v2.w, a2.w);
                a3.x = fmaf(g, v3.x, a3.x); a3.y = fmaf(g, v3.y, a3.y);
                a3.z = fmaf(g, v3.z, a3.z); a3.w = fmaf(g, v3.w, a3.w);
            }
        }
        const int fn = c*32 + 16;              // neighbor block (masked)
        su[(fn+ 0)*68+nn]=a0.x*mk; su[(fn+ 1)*68+nn]=a0.y*mk;
        su[(fn+ 2)*68+nn]=a0.z*mk; su[(fn+ 3)*68+nn]=a0.w*mk;
        su[(fn+ 4)*68+nn]=a1.x*mk; su[(fn+ 5)*68+nn]=a1.y*mk;
        su[(fn+ 6)*68+nn]=a1.z*mk; su[(fn+ 7)*68+nn]=a1.w*mk;
        su[(fn+ 8)*68+nn]=a2.x*mk; su[(fn+ 9)*68+nn]=a2.y*mk;
        su[(fn+10)*68+nn]=a2.z*mk; su[(fn+11)*68+nn]=a2.w*mk;
        su[(fn+12)*68+nn]=a3.x*mk; su[(fn+13)*68+nn]=a3.y*mk;
        su[(fn+14)*68+nn]=a3.z*mk; su[(fn+15)*68+nn]=a3.w*mk;

        const float Gm = G * mk;               // self block
        const float4* fp = (const float4*)(nf + (size_t)(n0+nn)*DD);
        const int fs = c*32;
        #pragma unroll
        for (int t4 = 0; t4 < 4; t4++) {
            float4 fv = __ldg(fp + t4);
            su[(fs+t4*4+0)*68+nn] = Gm*fv.x;  su[(fs+t4*4+1)*68+nn] = Gm*fv.y;
            su[(fs+t4*4+2)*68+nn] = Gm*fv.z;  su[(fs+t4*4+3)*68+nn] = Gm*fv.w;
        }
    }
    __syncthreads();

    // phase B: thread tile 4m x 4n; sw from L1-global, awT/u/theta from smem
    {
        const int mg  = (tid & 15) * 4;
        const int ng4 = (tid >> 4) * 4;
        float acc[4][4];
        #pragma unroll
        for (int a = 0; a < 4; a++)
            #pragma unroll
            for (int q = 0; q < 4; q++) acc[a][q] = 0.f;

        #pragma unroll 4
        for (int f = 0; f < 128; f++) {
            float4 w1 = __ldg((const float4*)(sw + f*64 + mg));
            float4 w2 = *(const float4*)&sawT[f*64 + mg];
            float4 uu = *(const float4*)&su  [f*68 + ng4];
            float4 tt = *(const float4*)&sth [f*68 + ng4];
            const float wm1[4] = {w1.x, w1.y, w1.z, w1.w};
            const float wm2[4] = {w2.x, w2.y, w2.z, w2.w};
            const float un[4]  = {uu.x, uu.y, uu.z, uu.w};
            const float tn[4]  = {tt.x, tt.y, tt.z, tt.w};
            #pragma unroll
            for (int a = 0; a < 4; a++)
                #pragma unroll
                for (int q = 0; q < 4; q++)
                    acc[a][q] = fmaf(wm1[a], un[q], fmaf(wm2[a], tn[q], acc[a][q]));
        }

        float mkq[4];
        #pragma unroll
        for (int q = 0; q < 4; q++) mkq[q] = node_mask[b*NN + n0 + ng4 + q];

        #pragma unroll
        for (int a = 0; a < 4; a++) {
            float v0 = acc[a][0], v1 = acc[a][1], v2 = acc[a][2], v3 = acc[a][3];
            v0 = (v0 >= 0.f) ? v0 : 0.01f*v0;  v1 = (v1 >= 0.f) ? v1 : 0.01f*v1;
            v2 = (v2 >= 0.f) ? v2 : 0.01f*v2;  v3 = (v3 >= 0.f) ? v3 : 0.01f*v3;
            float4 o4 = make_float4(v0*mkq[0], v1*mkq[1], v2*mkq[2], v3*mkq[3]);
            *(float4*)&out[((size_t)b*MM + mg + a)*NN + n0 + ng4] = o4;
        }
    }
}

// ---------------------------------------------------------------------------
extern "C" void kernel_launch(void* const* d_in, const int* in_sizes, int n_in,
                              void* d_out, int out_size)
{
    const float* pos       = (const float*)d_in[0];
    const float* node_fea  = (const float*)d_in[1];
    const float* node_mask = (const float*)d_in[2];
    const float* aw        = (const float*)d_in[3];
    const float* sw        = (const float*)d_in[4];
    const float* rw1       = (const float*)d_in[5];
    const float* rw2       = (const float*)d_in[6];
    float* out = (float*)d_out;

    cudaFuncSetAttribute(fuse_kernel,
        cudaFuncAttributeMaxDynamicSharedMemorySize, SM2F*4);

    knn_kernel<<<dim3(NN/32, BSZ*CC), 512>>>(pos, node_mask, rw1, rw2);
    fuse_kernel<<<BSZ*(NN/64), 256, SM2F*4>>>(node_fea, node_mask, aw, sw, out);
}